// round 1
// baseline (speedup 1.0000x reference)
#include <cuda_runtime.h>
#include <cstdint>

// Problem constants
#define NN 128
#define CC 64
#define TT 256
#define VV 25
#define DD 64
#define RR 16           // SE reduction dim (C/4)
#define FEAT 1600       // V*D = V*C
#define ROWS (NN*TT)    // 32768
#define TTILE 8         // t-frames per gemm block
#define ATSTRIDE 26     // padded v-dim (25 -> 26, pad slot zeroed)

typedef unsigned long long u64;

// ---------------- scratch (device globals; no allocations allowed) ----------
__device__ float g_pooled[NN*CC];
__device__ float g_gate[NN*4];
__device__ float g_Wf[NN*CC*DD];      // 2 MB
__device__ float g_bf[NN*DD];
__device__ float g_y[(size_t)ROWS*FEAT];   // 209.7 MB intermediate
__device__ float g_sum[FEAT];
__device__ float g_sumsq[FEAT];
__device__ float g_scale[FEAT];
__device__ float g_bias[FEAT];
__device__ short g_tsrc[CC*ATSTRIDE];  // gather table into raw smem tile
__device__ float g_tm[CC*ATSTRIDE];    // tanh(mask)+1, 0 on pad slots

// ---------------- f32x2 helpers ---------------------------------------------
__device__ __forceinline__ u64 pack2(float lo, float hi) {
    u64 r; asm("mov.b64 %0, {%1, %2};" : "=l"(r) : "f"(lo), "f"(hi)); return r;
}
__device__ __forceinline__ void unpack2(u64 v, float& lo, float& hi) {
    asm("mov.b64 {%0, %1}, %2;" : "=f"(lo), "=f"(hi) : "l"(v));
}
__device__ __forceinline__ u64 ffma2(u64 a, u64 b, u64 c) {
    u64 d; asm("fma.rn.f32x2 %0, %1, %2, %3;" : "=l"(d) : "l"(a), "l"(b), "l"(c));
    return d;
}

// ---------------- kernel 1: global average pool ------------------------------
__global__ void pool_kernel(const float* __restrict__ x0) {
    int nc = blockIdx.x;                 // 0..8191  (n*64 + c)
    const float4* p = (const float4*)(x0 + (size_t)nc * (TT*VV));
    float s = 0.f;
    for (int i = threadIdx.x; i < (TT*VV)/4; i += 256) {
        float4 v = p[i];
        s += v.x + v.y + v.z + v.w;
    }
    // block reduce
    for (int off = 16; off > 0; off >>= 1) s += __shfl_down_sync(0xffffffffu, s, off);
    __shared__ float red[8];
    int w = threadIdx.x >> 5, l = threadIdx.x & 31;
    if (l == 0) red[w] = s;
    __syncthreads();
    if (threadIdx.x == 0) {
        float t = 0.f;
        #pragma unroll
        for (int i = 0; i < 8; i++) t += red[i];
        g_pooled[nc] = t * (1.f / (TT*VV));
    }
}

// ---------------- kernel 2: SE gate ------------------------------------------
__global__ void gate_kernel(const float* __restrict__ fc1_w, const float* __restrict__ fc1_b,
                            const float* __restrict__ fc2_w, const float* __restrict__ fc2_b,
                            const int* __restrict__ epoch_p) {
    int n = threadIdx.x;
    if (n >= NN) return;
    float pooled[CC];
    #pragma unroll
    for (int c = 0; c < CC; c++) pooled[c] = g_pooled[n*CC + c];
    float h[RR];
    #pragma unroll
    for (int j = 0; j < RR; j++) {
        float s = fc1_b[j];
        #pragma unroll
        for (int c = 0; c < CC; c++) s += pooled[c] * fc1_w[j*CC + c];
        h[j] = s > 0.f ? s : 0.f;
    }
    float lg[4];
    #pragma unroll
    for (int k = 0; k < 4; k++) {
        float s = fc2_b[k];
        #pragma unroll
        for (int j = 0; j < RR; j++) s += h[j] * fc2_w[k*RR + j];
        lg[k] = s;
    }
    int ep = *epoch_p;
    float tao = (ep >= 60) ? 1.0f : (-(29.0f / 60.0f) * (float)ep + 30.0f);
    float inv = 1.0f / tao;
    float m = lg[0];
    #pragma unroll
    for (int k = 1; k < 4; k++) m = fmaxf(m, lg[k]);
    float e[4], sum = 0.f;
    #pragma unroll
    for (int k = 0; k < 4; k++) { e[k] = __expf((lg[k] - m) * inv); sum += e[k]; }
    float r = 1.0f / sum;
    #pragma unroll
    for (int k = 0; k < 4; k++) g_gate[n*4 + k] = e[k] * r;
}

// ---------------- kernel 3: fused weights + gather tables + zero stats -------
__global__ void prep_kernel(const float* __restrict__ W, const float* __restrict__ b,
                            const float* __restrict__ mask, const int* __restrict__ shift_in) {
    int blk = blockIdx.x;
    int tid = threadIdx.x;
    if (blk < NN) {
        int n = blk;
        float g0 = g_gate[n*4+0], g1 = g_gate[n*4+1], g2 = g_gate[n*4+2], g3 = g_gate[n*4+3];
        for (int i = tid; i < CC*DD; i += 256)
            g_Wf[n*CC*DD + i] = g0*W[i] + g1*W[CC*DD + i] + g2*W[2*CC*DD + i] + g3*W[3*CC*DD + i];
        if (tid < DD)
            g_bf[n*DD + tid] = g0*b[tid] + g1*b[DD+tid] + g2*b[2*DD+tid] + g3*b[3*DD+tid];
    } else {
        for (int j = tid; j < CC*ATSTRIDE; j += 256) {
            int c_out = j / ATSTRIDE, v_out = j % ATSTRIDE;
            if (v_out < VV) {
                int src = shift_in[v_out*CC + c_out];
                int vp = src >> 6, cp = src & 63;          // C == 64
                g_tsrc[j] = (short)(cp * (TTILE*VV) + vp); // index into raw smem tile (+ t*25 at runtime)
                g_tm[j] = tanhf(mask[v_out*CC + c_out]) + 1.0f;
            } else {
                g_tsrc[j] = 0;
                g_tm[j] = 0.f;
            }
        }
        for (int f = tid; f < FEAT; f += 256) { g_sum[f] = 0.f; g_sumsq[f] = 0.f; }
    }
}

// ---------------- kernel 4: per-sample GEMM (f32x2) --------------------------
// block: 256 threads = 8 warps; block handles (n, 8 consecutive t).
// warp w handles frame t0+w; lane l owns d-pair (2l, 2l+1), all 25 v.
#define RAW_F (CC*TTILE*VV)        // 12800
#define WF_F  (CC*DD)              // 4096
#define TM_F  (CC*ATSTRIDE)        // 1664
#define AT_F  (8*CC*ATSTRIDE)      // 13312
#define GEMM_SMEM_BYTES ((RAW_F + WF_F + TM_F + AT_F)*4 + TM_F*2)

__global__ void __launch_bounds__(256, 1) gemm_kernel(const float* __restrict__ x0) {
    extern __shared__ float smem[];
    float* rawsm = smem;                   // [c][t][v]  64 x 200
    float* Wfs   = rawsm + RAW_F;          // [c][d]
    float* tms   = Wfs + WF_F;
    float* Ats   = tms + TM_F;             // 8 x [c][26]
    short* tss   = (short*)(Ats + AT_F);

    int bid = blockIdx.x;
    int n  = bid >> 5;
    int t0 = (bid & 31) * TTILE;
    int tid = threadIdx.x;

    { // stage Wf
        const float4* ws = (const float4*)(g_Wf + (size_t)n * WF_F);
        float4* wd = (float4*)Wfs;
        for (int i = tid; i < WF_F/4; i += 256) wd[i] = ws[i];
    }
    for (int j = tid; j < TM_F; j += 256) { tms[j] = g_tm[j]; tss[j] = g_tsrc[j]; }
    { // stage raw x0 tile: per c, 200 contiguous floats
        const float* xb = x0 + (size_t)n * CC * (TT*VV) + t0 * VV;
        for (int i = tid; i < RAW_F/4; i += 256) {
            int c = i / 50, q = i - c * 50;
            float4 v = *(const float4*)(xb + c * (TT*VV) + q*4);
            *(float4*)(rawsm + c * (TTILE*VV) + q*4) = v;
        }
    }
    __syncthreads();

    int w = tid >> 5, l = tid & 31;
    // gather + mask into transposed padded At[c][v]
    float* At = Ats + w * TM_F;
    const float* rw = rawsm + w * VV;
    for (int j = l; j < TM_F; j += 32) At[j] = rw[tss[j]] * tms[j];
    __syncwarp();

    int d0 = 2*l;
    float b0 = g_bf[n*DD + d0], b1 = g_bf[n*DD + d0 + 1];
    u64 acc0[13], acc1[13];
    u64 bb0 = pack2(b0, b0), bb1 = pack2(b1, b1);
    #pragma unroll
    for (int vp = 0; vp < 13; vp++) { acc0[vp] = bb0; acc1[vp] = bb1; }

    #pragma unroll 2
    for (int c = 0; c < CC; c++) {
        float2 wv = *(const float2*)(Wfs + c*DD + d0);
        u64 s0 = pack2(wv.x, wv.x);
        u64 s1 = pack2(wv.y, wv.y);
        const u64* arow = (const u64*)(At + c*ATSTRIDE);
        #pragma unroll
        for (int vp = 0; vp < 13; vp++) {
            u64 a2 = arow[vp];
            acc0[vp] = ffma2(a2, s0, acc0[vp]);
            acc1[vp] = ffma2(a2, s1, acc1[vp]);
        }
    }

    float* yrow = g_y + (size_t)(n*TT + t0 + w) * FEAT;
    #pragma unroll
    for (int vp = 0; vp < 13; vp++) {
        float a0, a1, c0, c1;
        unpack2(acc0[vp], a0, a1);
        unpack2(acc1[vp], c0, c1);
        int v = 2*vp;
        *(float2*)(yrow + v*DD + d0) = make_float2(a0, c0);
        if (v + 1 < VV)
            *(float2*)(yrow + (v+1)*DD + d0) = make_float2(a1, c1);
    }
}

// ---------------- kernel 5: BN stats over 32768 rows -------------------------
__global__ void stats_kernel() {
    int row0 = blockIdx.x * 64;          // 512 blocks x 64 rows
    float s[7], q[7];
    #pragma unroll
    for (int k = 0; k < 7; k++) { s[k] = 0.f; q[k] = 0.f; }
    for (int r = 0; r < 64; r++) {
        const float* yr = g_y + (size_t)(row0 + r) * FEAT;
        #pragma unroll
        for (int k = 0; k < 7; k++) {
            int f = threadIdx.x + k*256;
            if (f < FEAT) { float v = yr[f]; s[k] += v; q[k] += v*v; }
        }
    }
    #pragma unroll
    for (int k = 0; k < 7; k++) {
        int f = threadIdx.x + k*256;
        if (f < FEAT) { atomicAdd(&g_sum[f], s[k]); atomicAdd(&g_sumsq[f], q[k]); }
    }
}

// ---------------- kernel 6: finalize BN params (with shift_out fold) ---------
__global__ void finalize_kernel(const int* __restrict__ shift_out,
                                const float* __restrict__ gamma,
                                const float* __restrict__ beta) {
    int f = blockIdx.x * 256 + threadIdx.x;
    if (f >= FEAT) return;
    int s = shift_out[f];
    const float invn = 1.0f / (float)ROWS;
    float mu = g_sum[s] * invn;
    float var = g_sumsq[s] * invn - mu * mu;
    float sc = gamma[f] * rsqrtf(var + 1e-5f);
    g_scale[f] = sc;
    g_bias[f] = beta[f] - mu * sc;
}

// ---------------- kernel 7: shift-out + BN + residual + relu + transpose -----
#define FINAL_SMEM_BYTES ((TTILE*FEAT + FEAT + FEAT)*4 + FEAT*4)
__global__ void __launch_bounds__(256) final_kernel(const float* __restrict__ x0,
                                                    const int* __restrict__ shift_out,
                                                    float* __restrict__ out) {
    extern __shared__ float fs[];
    float* ysm = fs;                  // 8 x 1600
    float* sc  = fs + TTILE*FEAT;     // 1600
    float* bi  = sc + FEAT;           // 1600
    int*   so  = (int*)(bi + FEAT);   // 1600

    int bid = blockIdx.x;
    int n  = bid >> 5;
    int t0 = (bid & 31) * TTILE;
    int tid = threadIdx.x;

    { // stage 8 y rows (contiguous)
        const float4* ys = (const float4*)(g_y + (size_t)(n*TT + t0) * FEAT);
        float4* yd = (float4*)ysm;
        for (int i = tid; i < (TTILE*FEAT)/4; i += 256) yd[i] = ys[i];
    }
    for (int f = tid; f < FEAT; f += 256) {
        sc[f] = g_scale[f];
        bi[f] = g_bias[f];
        so[f] = shift_out[f];
    }
    __syncthreads();

    size_t base = (size_t)n * CC * (TT*VV) + (size_t)t0 * VV;
    for (int e = tid; e < TTILE*FEAT; e += 256) {
        int d = e / (TTILE*VV);                 // /200
        int r = e - d * (TTILE*VV);
        int tl = r / VV;
        int v = r - tl * VV;
        int f = v*DD + d;
        float val = ysm[tl*FEAT + so[f]] * sc[f] + bi[f];
        size_t idx = base + (size_t)d * (TT*VV) + r;
        float o = val + x0[idx];
        out[idx] = o > 0.f ? o : 0.f;
    }
}

// ---------------- launcher ---------------------------------------------------
extern "C" void kernel_launch(void* const* d_in, const int* in_sizes, int n_in,
                              void* d_out, int out_size) {
    const float* x0       = (const float*)d_in[0];
    const int*   epoch    = (const int*)  d_in[1];
    const float* fc1_w    = (const float*)d_in[2];
    const float* fc1_b    = (const float*)d_in[3];
    const float* fc2_w    = (const float*)d_in[4];
    const float* fc2_b    = (const float*)d_in[5];
    const float* W        = (const float*)d_in[6];
    const float* b        = (const float*)d_in[7];
    const float* mask     = (const float*)d_in[8];
    const float* gamma    = (const float*)d_in[9];
    const float* beta     = (const float*)d_in[10];
    const int*   shift_in = (const int*)  d_in[11];
    const int*   shift_out= (const int*)  d_in[12];
    float* out = (float*)d_out;

    cudaFuncSetAttribute(gemm_kernel, cudaFuncAttributeMaxDynamicSharedMemorySize, GEMM_SMEM_BYTES);
    cudaFuncSetAttribute(final_kernel, cudaFuncAttributeMaxDynamicSharedMemorySize, FINAL_SMEM_BYTES);

    pool_kernel<<<NN*CC, 256>>>(x0);
    gate_kernel<<<1, 128>>>(fc1_w, fc1_b, fc2_w, fc2_b, epoch);
    prep_kernel<<<NN + 1, 256>>>(W, b, mask, shift_in);
    gemm_kernel<<<NN * (TT/TTILE), 256, GEMM_SMEM_BYTES>>>(x0);
    stats_kernel<<<ROWS/64, 256>>>();
    finalize_kernel<<<(FEAT + 255)/256, 256>>>(shift_out, gamma, beta);
    final_kernel<<<NN * (TT/TTILE), 256, FINAL_SMEM_BYTES>>>(x0, shift_out, out);
}

// round 2
// speedup vs baseline: 1.6998x; 1.6998x over previous
#include <cuda_runtime.h>
#include <cstdint>

// Problem constants
#define NN 128
#define CC 64
#define TT 256
#define VV 25
#define DD 64
#define RR 16           // SE reduction dim (C/4)
#define FEAT 1600       // V*D = V*C
#define ROWS (NN*TT)    // 32768
#define TTILE 8         // t-frames per gemm block
#define ATSTRIDE 26     // padded v-dim (25 -> 26, pad slot zeroed)

typedef unsigned long long u64;

// ---------------- scratch (device globals; no allocations allowed) ----------
__device__ float g_pooled[NN*CC];
__device__ float g_gate[NN*4];
__device__ float g_Wf[NN*CC*DD];      // 2 MB
__device__ float g_bf[NN*DD];
__device__ float g_y[(size_t)ROWS*FEAT];   // 209.7 MB intermediate
__device__ float g_sum[FEAT];
__device__ float g_sumsq[FEAT];
__device__ float g_scale[FEAT];
__device__ float g_bias[FEAT];
__device__ short g_tsrc[CC*ATSTRIDE];  // gather table into raw smem tile
__device__ float g_tm[CC*ATSTRIDE];    // tanh(mask)+1, 0 on pad slots

// ---------------- f32x2 helpers ---------------------------------------------
__device__ __forceinline__ u64 pack2(float lo, float hi) {
    u64 r; asm("mov.b64 %0, {%1, %2};" : "=l"(r) : "f"(lo), "f"(hi)); return r;
}
__device__ __forceinline__ void unpack2(u64 v, float& lo, float& hi) {
    asm("mov.b64 {%0, %1}, %2;" : "=f"(lo), "=f"(hi) : "l"(v));
}
__device__ __forceinline__ u64 ffma2(u64 a, u64 b, u64 c) {
    u64 d; asm("fma.rn.f32x2 %0, %1, %2, %3;" : "=l"(d) : "l"(a), "l"(b), "l"(c));
    return d;
}

// ---------------- kernel 1: global average pool ------------------------------
__global__ void pool_kernel(const float* __restrict__ x0) {
    int nc = blockIdx.x;                 // 0..8191  (n*64 + c)
    const float4* p = (const float4*)(x0 + (size_t)nc * (TT*VV));
    float s = 0.f;
    for (int i = threadIdx.x; i < (TT*VV)/4; i += 256) {
        float4 v = p[i];
        s += v.x + v.y + v.z + v.w;
    }
    for (int off = 16; off > 0; off >>= 1) s += __shfl_down_sync(0xffffffffu, s, off);
    __shared__ float red[8];
    int w = threadIdx.x >> 5, l = threadIdx.x & 31;
    if (l == 0) red[w] = s;
    __syncthreads();
    if (threadIdx.x == 0) {
        float t = 0.f;
        #pragma unroll
        for (int i = 0; i < 8; i++) t += red[i];
        g_pooled[nc] = t * (1.f / (TT*VV));
    }
}

// ---------------- kernel 2: SE gate ------------------------------------------
__global__ void gate_kernel(const float* __restrict__ fc1_w, const float* __restrict__ fc1_b,
                            const float* __restrict__ fc2_w, const float* __restrict__ fc2_b,
                            const int* __restrict__ epoch_p) {
    int n = threadIdx.x;
    if (n >= NN) return;
    float pooled[CC];
    #pragma unroll
    for (int c = 0; c < CC; c++) pooled[c] = g_pooled[n*CC + c];
    float h[RR];
    #pragma unroll
    for (int j = 0; j < RR; j++) {
        float s = fc1_b[j];
        #pragma unroll
        for (int c = 0; c < CC; c++) s += pooled[c] * fc1_w[j*CC + c];
        h[j] = s > 0.f ? s : 0.f;
    }
    float lg[4];
    #pragma unroll
    for (int k = 0; k < 4; k++) {
        float s = fc2_b[k];
        #pragma unroll
        for (int j = 0; j < RR; j++) s += h[j] * fc2_w[k*RR + j];
        lg[k] = s;
    }
    int ep = *epoch_p;
    float tao = (ep >= 60) ? 1.0f : (-(29.0f / 60.0f) * (float)ep + 30.0f);
    float inv = 1.0f / tao;
    float m = lg[0];
    #pragma unroll
    for (int k = 1; k < 4; k++) m = fmaxf(m, lg[k]);
    float e[4], sum = 0.f;
    #pragma unroll
    for (int k = 0; k < 4; k++) { e[k] = __expf((lg[k] - m) * inv); sum += e[k]; }
    float r = 1.0f / sum;
    #pragma unroll
    for (int k = 0; k < 4; k++) g_gate[n*4 + k] = e[k] * r;
}

// ---------------- kernel 3: fused weights + gather tables + zero stats -------
__global__ void prep_kernel(const float* __restrict__ W, const float* __restrict__ b,
                            const float* __restrict__ mask, const int* __restrict__ shift_in) {
    int blk = blockIdx.x;
    int tid = threadIdx.x;
    if (blk < NN) {
        int n = blk;
        float g0 = g_gate[n*4+0], g1 = g_gate[n*4+1], g2 = g_gate[n*4+2], g3 = g_gate[n*4+3];
        for (int i = tid; i < CC*DD; i += 256)
            g_Wf[n*CC*DD + i] = g0*W[i] + g1*W[CC*DD + i] + g2*W[2*CC*DD + i] + g3*W[3*CC*DD + i];
        if (tid < DD)
            g_bf[n*DD + tid] = g0*b[tid] + g1*b[DD+tid] + g2*b[2*DD+tid] + g3*b[3*DD+tid];
    } else {
        for (int j = tid; j < CC*ATSTRIDE; j += 256) {
            int c_out = j / ATSTRIDE, v_out = j % ATSTRIDE;
            if (v_out < VV) {
                int src = shift_in[v_out*CC + c_out];
                int vp = src >> 6, cp = src & 63;          // C == 64
                g_tsrc[j] = (short)(cp * (TTILE*VV) + vp); // index into raw smem tile (+ t*25 at runtime)
                g_tm[j] = tanhf(mask[v_out*CC + c_out]) + 1.0f;
            } else {
                g_tsrc[j] = 0;
                g_tm[j] = 0.f;
            }
        }
        for (int f = tid; f < FEAT; f += 256) { g_sum[f] = 0.f; g_sumsq[f] = 0.f; }
    }
}

// ---------------- kernel 4: per-sample GEMM (f32x2) --------------------------
// block: 256 threads = 8 warps; block handles (n, 8 consecutive t).
// warp w handles frame t0+w; lane l owns d-pair (2l, 2l+1), all 25 v.
// Wf + gather tables read from global (L1/L2-hot) to fit 2 blocks/SM.
#define RAW_F (CC*TTILE*VV)        // 12800
#define TM_F  (CC*ATSTRIDE)        // 1664
#define AT_F  (8*CC*ATSTRIDE)      // 13312
#define GEMM_SMEM_BYTES ((RAW_F + AT_F)*4)

__global__ void __launch_bounds__(256, 2) gemm_kernel(const float* __restrict__ x0) {
    extern __shared__ float smem[];
    float* rawsm = smem;                   // [c][t][v]  64 x 200
    float* Ats   = rawsm + RAW_F;          // 8 x [c][26]

    int bid = blockIdx.x;
    int n  = bid >> 5;
    int t0 = (bid & 31) * TTILE;
    int tid = threadIdx.x;

    { // stage raw x0 tile: per c, 200 contiguous floats
        const float* xb = x0 + (size_t)n * CC * (TT*VV) + t0 * VV;
        for (int i = tid; i < RAW_F/4; i += 256) {
            int c = i / 50, q = i - c * 50;
            float4 v = *(const float4*)(xb + c * (TT*VV) + q*4);
            *(float4*)(rawsm + c * (TTILE*VV) + q*4) = v;
        }
    }
    __syncthreads();

    int w = tid >> 5, l = tid & 31;
    // gather + mask into transposed padded At[c][v]  (tables from global, L1-hot)
    float* At = Ats + w * TM_F;
    const float* rw = rawsm + w * VV;
    {
        const short* __restrict__ ts = g_tsrc;
        const float* __restrict__ tm = g_tm;
        #pragma unroll 4
        for (int j = l; j < TM_F; j += 32) At[j] = rw[ts[j]] * tm[j];
    }
    __syncwarp();

    int d0 = 2*l;
    float b0 = g_bf[n*DD + d0], b1 = g_bf[n*DD + d0 + 1];
    u64 acc0[13], acc1[13];
    u64 bb0 = pack2(b0, b0), bb1 = pack2(b1, b1);
    #pragma unroll
    for (int vp = 0; vp < 13; vp++) { acc0[vp] = bb0; acc1[vp] = bb1; }

    const float* Wg = g_Wf + (size_t)n * (CC*DD) + d0;
    #pragma unroll
    for (int cb = 0; cb < CC; cb += 8) {
        float2 wv[8];
        #pragma unroll
        for (int i = 0; i < 8; i++)
            wv[i] = *(const float2*)(Wg + (cb + i) * DD);
        #pragma unroll
        for (int i = 0; i < 8; i++) {
            u64 s0 = pack2(wv[i].x, wv[i].x);
            u64 s1 = pack2(wv[i].y, wv[i].y);
            const u64* arow = (const u64*)(At + (cb + i)*ATSTRIDE);
            #pragma unroll
            for (int vp = 0; vp < 13; vp++) {
                u64 a2 = arow[vp];
                acc0[vp] = ffma2(a2, s0, acc0[vp]);
                acc1[vp] = ffma2(a2, s1, acc1[vp]);
            }
        }
    }

    float* yrow = g_y + (size_t)(n*TT + t0 + w) * FEAT;
    #pragma unroll
    for (int vp = 0; vp < 13; vp++) {
        float a0, a1, c0, c1;
        unpack2(acc0[vp], a0, a1);
        unpack2(acc1[vp], c0, c1);
        int v = 2*vp;
        *(float2*)(yrow + v*DD + d0) = make_float2(a0, c0);
        if (v + 1 < VV)
            *(float2*)(yrow + (v+1)*DD + d0) = make_float2(a1, c1);
    }
}

// ---------------- kernel 5: BN stats over 32768 rows -------------------------
__global__ void stats_kernel() {
    int row0 = blockIdx.x * 64;          // 512 blocks x 64 rows
    float s[7], q[7];
    #pragma unroll
    for (int k = 0; k < 7; k++) { s[k] = 0.f; q[k] = 0.f; }
    for (int r = 0; r < 64; r++) {
        const float* yr = g_y + (size_t)(row0 + r) * FEAT;
        #pragma unroll
        for (int k = 0; k < 7; k++) {
            int f = threadIdx.x + k*256;
            if (f < FEAT) { float v = yr[f]; s[k] += v; q[k] += v*v; }
        }
    }
    #pragma unroll
    for (int k = 0; k < 7; k++) {
        int f = threadIdx.x + k*256;
        if (f < FEAT) { atomicAdd(&g_sum[f], s[k]); atomicAdd(&g_sumsq[f], q[k]); }
    }
}

// ---------------- kernel 6: finalize BN params (with shift_out fold) ---------
__global__ void finalize_kernel(const int* __restrict__ shift_out,
                                const float* __restrict__ gamma,
                                const float* __restrict__ beta) {
    int f = blockIdx.x * 256 + threadIdx.x;
    if (f >= FEAT) return;
    int s = shift_out[f];
    const float invn = 1.0f / (float)ROWS;
    float mu = g_sum[s] * invn;
    float var = g_sumsq[s] * invn - mu * mu;
    float sc = gamma[f] * rsqrtf(var + 1e-5f);
    g_scale[f] = sc;
    g_bias[f] = beta[f] - mu * sc;
}

// ---------------- kernel 7: shift-out + BN + residual + relu + transpose -----
// Conflict-free two-phase: gather (lanes over consecutive f -> banks = d mod 32,
// no conflict) into padded zsm [v*65+d], then transposed d-major write-out.
#define ZSTRIDE 1632                     // 4 frames x (25*65 pad + align)
#define FINAL_SMEM_BYTES ((TTILE*FEAT + 4*ZSTRIDE)*4)
__global__ void __launch_bounds__(256, 2) final_kernel(const float* __restrict__ x0,
                                                       const int* __restrict__ shift_out,
                                                       float* __restrict__ out) {
    extern __shared__ float fs[];
    float* ysm = fs;                      // 8 x 1600
    float* zsm = fs + TTILE*FEAT;         // 4 x 1632 (v*65+d layout)

    int bid = blockIdx.x;
    int n  = bid >> 5;
    int t0 = (bid & 31) * TTILE;
    int tid = threadIdx.x;

    { // stage 8 y rows (contiguous, coalesced)
        const float4* ys = (const float4*)(g_y + (size_t)(n*TT + t0) * FEAT);
        float4* yd = (float4*)ysm;
        for (int i = tid; i < (TTILE*FEAT)/4; i += 256) yd[i] = ys[i];
    }
    __syncthreads();

    size_t nbase = (size_t)n * CC * (TT*VV);
    #pragma unroll
    for (int half = 0; half < 2; half++) {
        // phase 1: BN gather into zsm (conflict-free)
        #pragma unroll
        for (int tl = 0; tl < 4; tl++) {
            const float* yr = ysm + (half*4 + tl)*FEAT;
            for (int f = tid; f < FEAT; f += 256) {
                int v = f >> 6, d = f & 63;
                float val = yr[shift_out[f]] * g_scale[f] + g_bias[f];
                zsm[tl*ZSTRIDE + v*65 + d] = val;
            }
        }
        __syncthreads();
        // phase 2: transposed write-out  e = d*100 + tl*25 + v
        for (int e = tid; e < 4*FEAT; e += 256) {
            int d = e / 100;
            int r = e - d * 100;
            int tl = r / 25;
            int v = r - tl * 25;
            float z = zsm[tl*ZSTRIDE + v*65 + d];
            size_t idx = nbase + (size_t)d * (TT*VV) + (size_t)(t0 + half*4 + tl) * VV + v;
            float o = z + x0[idx];
            out[idx] = o > 0.f ? o : 0.f;
        }
        __syncthreads();
    }
}

// ---------------- launcher ---------------------------------------------------
extern "C" void kernel_launch(void* const* d_in, const int* in_sizes, int n_in,
                              void* d_out, int out_size) {
    const float* x0       = (const float*)d_in[0];
    const int*   epoch    = (const int*)  d_in[1];
    const float* fc1_w    = (const float*)d_in[2];
    const float* fc1_b    = (const float*)d_in[3];
    const float* fc2_w    = (const float*)d_in[4];
    const float* fc2_b    = (const float*)d_in[5];
    const float* W        = (const float*)d_in[6];
    const float* b        = (const float*)d_in[7];
    const float* mask     = (const float*)d_in[8];
    const float* gamma    = (const float*)d_in[9];
    const float* beta     = (const float*)d_in[10];
    const int*   shift_in = (const int*)  d_in[11];
    const int*   shift_out= (const int*)  d_in[12];
    float* out = (float*)d_out;

    cudaFuncSetAttribute(gemm_kernel, cudaFuncAttributeMaxDynamicSharedMemorySize, GEMM_SMEM_BYTES);
    cudaFuncSetAttribute(final_kernel, cudaFuncAttributeMaxDynamicSharedMemorySize, FINAL_SMEM_BYTES);

    pool_kernel<<<NN*CC, 256>>>(x0);
    gate_kernel<<<1, 128>>>(fc1_w, fc1_b, fc2_w, fc2_b, epoch);
    prep_kernel<<<NN + 1, 256>>>(W, b, mask, shift_in);
    gemm_kernel<<<NN * (TT/TTILE), 256, GEMM_SMEM_BYTES>>>(x0);
    stats_kernel<<<ROWS/64, 256>>>();
    finalize_kernel<<<(FEAT + 255)/256, 256>>>(shift_out, gamma, beta);
    final_kernel<<<NN * (TT/TTILE), 256, FINAL_SMEM_BYTES>>>(x0, shift_out, out);
}

// round 3
// speedup vs baseline: 1.7922x; 1.0543x over previous
#include <cuda_runtime.h>
#include <cstdint>

// Problem constants
#define NN 128
#define CC 64
#define TT 256
#define VV 25
#define DD 64
#define RR 16           // SE reduction dim (C/4)
#define FEAT 1600       // V*D
#define ROWS (NN*TT)    // 32768
#define TTILE 8         // t-frames per gemm tile
#define NTILES 4        // tiles per block
#define ATSTRIDE 28     // padded v-dim (16B-aligned rows for LDS.128)

typedef unsigned long long u64;

// ---------------- scratch (device globals; no allocations allowed) ----------
__device__ float g_pooled[NN*CC];
__device__ float g_gate[NN*4];
__device__ float g_Wf[NN*CC*DD];      // 2 MB
__device__ float g_bf[NN*DD];
__device__ float g_y[(size_t)ROWS*FEAT];   // 209.7 MB intermediate
__device__ float g_sum[FEAT];
__device__ float g_sumsq[FEAT];
__device__ float g_scale[FEAT];
__device__ float g_bias[FEAT];
__device__ short g_tsrc[CC*ATSTRIDE];  // gather table into raw smem tile
__device__ float g_tm[CC*ATSTRIDE];    // tanh(mask)+1, 0 on pad slots

// ---------------- f32x2 helpers ---------------------------------------------
__device__ __forceinline__ u64 pack2(float lo, float hi) {
    u64 r; asm("mov.b64 %0, {%1, %2};" : "=l"(r) : "f"(lo), "f"(hi)); return r;
}
__device__ __forceinline__ void unpack2(u64 v, float& lo, float& hi) {
    asm("mov.b64 {%0, %1}, %2;" : "=f"(lo), "=f"(hi) : "l"(v));
}
__device__ __forceinline__ u64 ffma2(u64 a, u64 b, u64 c) {
    u64 d; asm("fma.rn.f32x2 %0, %1, %2, %3;" : "=l"(d) : "l"(a), "l"(b), "l"(c));
    return d;
}
__device__ __forceinline__ void cp_async16(float* dst_smem, const void* src) {
    unsigned d = (unsigned)__cvta_generic_to_shared(dst_smem);
    asm volatile("cp.async.cg.shared.global [%0], [%1], 16;" :: "r"(d), "l"(src));
}
#define CP_COMMIT() asm volatile("cp.async.commit_group;")
#define CP_WAIT0()  asm volatile("cp.async.wait_group 0;")

// ---------------- kernel 1: global average pool ------------------------------
__global__ void pool_kernel(const float* __restrict__ x0) {
    int nc = blockIdx.x;                 // 0..8191  (n*64 + c)
    const float4* p = (const float4*)(x0 + (size_t)nc * (TT*VV));
    float s = 0.f;
    for (int i = threadIdx.x; i < (TT*VV)/4; i += 256) {
        float4 v = p[i];
        s += v.x + v.y + v.z + v.w;
    }
    for (int off = 16; off > 0; off >>= 1) s += __shfl_down_sync(0xffffffffu, s, off);
    __shared__ float red[8];
    int w = threadIdx.x >> 5, l = threadIdx.x & 31;
    if (l == 0) red[w] = s;
    __syncthreads();
    if (threadIdx.x == 0) {
        float t = 0.f;
        #pragma unroll
        for (int i = 0; i < 8; i++) t += red[i];
        g_pooled[nc] = t * (1.f / (TT*VV));
    }
}

// ---------------- kernel 2: SE gate ------------------------------------------
__global__ void gate_kernel(const float* __restrict__ fc1_w, const float* __restrict__ fc1_b,
                            const float* __restrict__ fc2_w, const float* __restrict__ fc2_b,
                            const int* __restrict__ epoch_p) {
    int n = threadIdx.x;
    if (n >= NN) return;
    float pooled[CC];
    #pragma unroll
    for (int c = 0; c < CC; c++) pooled[c] = g_pooled[n*CC + c];
    float h[RR];
    #pragma unroll
    for (int j = 0; j < RR; j++) {
        float s = fc1_b[j];
        #pragma unroll
        for (int c = 0; c < CC; c++) s += pooled[c] * fc1_w[j*CC + c];
        h[j] = s > 0.f ? s : 0.f;
    }
    float lg[4];
    #pragma unroll
    for (int k = 0; k < 4; k++) {
        float s = fc2_b[k];
        #pragma unroll
        for (int j = 0; j < RR; j++) s += h[j] * fc2_w[k*RR + j];
        lg[k] = s;
    }
    int ep = *epoch_p;
    float tao = (ep >= 60) ? 1.0f : (-(29.0f / 60.0f) * (float)ep + 30.0f);
    float inv = 1.0f / tao;
    float m = lg[0];
    #pragma unroll
    for (int k = 1; k < 4; k++) m = fmaxf(m, lg[k]);
    float e[4], sum = 0.f;
    #pragma unroll
    for (int k = 0; k < 4; k++) { e[k] = __expf((lg[k] - m) * inv); sum += e[k]; }
    float r = 1.0f / sum;
    #pragma unroll
    for (int k = 0; k < 4; k++) g_gate[n*4 + k] = e[k] * r;
}

// ---------------- kernel 3: fused weights + gather tables + zero stats -------
__global__ void prep_kernel(const float* __restrict__ W, const float* __restrict__ b,
                            const float* __restrict__ mask, const int* __restrict__ shift_in) {
    int blk = blockIdx.x;
    int tid = threadIdx.x;
    if (blk < NN) {
        int n = blk;
        float g0 = g_gate[n*4+0], g1 = g_gate[n*4+1], g2 = g_gate[n*4+2], g3 = g_gate[n*4+3];
        for (int i = tid; i < CC*DD; i += 256)
            g_Wf[n*CC*DD + i] = g0*W[i] + g1*W[CC*DD + i] + g2*W[2*CC*DD + i] + g3*W[3*CC*DD + i];
        if (tid < DD)
            g_bf[n*DD + tid] = g0*b[tid] + g1*b[DD+tid] + g2*b[2*DD+tid] + g3*b[3*DD+tid];
    } else {
        for (int j = tid; j < CC*ATSTRIDE; j += 256) {
            int c_out = j / ATSTRIDE, v_out = j % ATSTRIDE;
            if (v_out < VV) {
                int src = shift_in[v_out*CC + c_out];
                int vp = src >> 6, cp = src & 63;          // C == 64
                g_tsrc[j] = (short)(cp * (TTILE*VV) + vp); // index into raw smem tile (+ t*25 at runtime)
                g_tm[j] = tanhf(mask[v_out*CC + c_out]) + 1.0f;
            } else {
                g_tsrc[j] = 0;
                g_tm[j] = 0.f;
            }
        }
        for (int f = tid; f < FEAT; f += 256) { g_sum[f] = 0.f; g_sumsq[f] = 0.f; }
    }
}

// ---------------- kernel 4: persistent pipelined GEMM + fused BN stats -------
// 1024 blocks; block = (n = bid>>3, q8 = bid&7); 4 tiles of 8 frames each.
// 8 warps/block; warp w = frame w of the tile; lane l owns d-pair (2l, 2l+1).
#define RAW_F (CC*TTILE*VV)        // 12800
#define TM_F  (CC*ATSTRIDE)        // 1792
#define AT_F  (8*TM_F)             // 14336
#define WF_F  (CC*DD)              // 4096
#define GEMM_SMEM_F (RAW_F + AT_F + WF_F + TM_F + FEAT + FEAT + DD + TM_F/2)
#define GEMM_SMEM_BYTES (GEMM_SMEM_F*4)

__global__ void __launch_bounds__(256, 1) gemm_kernel(const float* __restrict__ x0) {
    extern __shared__ float smem[];
    float* raw  = smem;                 // [c][t][v] 64 x 200
    float* Ats  = raw + RAW_F;          // 8 x [c][28]  (reused as stats staging)
    float* Wfs  = Ats + AT_F;           // [c][d]
    float* tms  = Wfs + WF_F;           // 64 x 28
    float* ssum = tms + TM_F;           // [1600]
    float* ssq  = ssum + FEAT;          // [1600]
    float* bfs  = ssq + FEAT;           // [64]
    short* tss  = (short*)(bfs + DD);   // 64 x 28

    int bid = blockIdx.x;
    int n   = bid >> 3;
    int q8  = bid & 7;
    int tid = threadIdx.x;
    int w = tid >> 5, l = tid & 31;

    // block-start staging (covered by first loop-top __syncthreads)
    {
        const float4* ws = (const float4*)(g_Wf + (size_t)n * WF_F);
        float4* wd = (float4*)Wfs;
        for (int i = tid; i < WF_F/4; i += 256) wd[i] = ws[i];
        for (int j = tid; j < TM_F; j += 256) { tms[j] = g_tm[j]; tss[j] = g_tsrc[j]; }
        for (int f = tid; f < FEAT; f += 256) { ssum[f] = 0.f; ssq[f] = 0.f; }
        if (tid < DD) bfs[tid] = g_bf[n*DD + tid];
    }

    const float* xbase = x0 + (size_t)n * CC * (TT*VV);

    // prefetch tile 0
    {
        const float* xb = xbase + (q8*32) * VV;
        #pragma unroll
        for (int k = 0; k < 13; k++) {
            int i = tid + k*256;
            if (i < RAW_F/4) {
                int c = i / 50, qq = i - c*50;
                cp_async16(raw + c*(TTILE*VV) + qq*4, xb + c*(TT*VV) + qq*4);
            }
        }
        CP_COMMIT();
    }

    int d0 = 2*l;
    float* At = Ats + w * TM_F;
    const float* rw = raw + w * VV;

    for (int it = 0; it < NTILES; it++) {
        int t0 = q8*32 + it*TTILE;
        CP_WAIT0();
        __syncthreads();                       // raw tile ready (and prev reduce done)

        // gather + mask into transposed padded At[c][28]
        #pragma unroll 4
        for (int j = l; j < TM_F; j += 32) At[j] = rw[tss[j]] * tms[j];
        __syncthreads();                       // raw now free

        // prefetch next tile (DMA overlaps compute)
        if (it + 1 < NTILES) {
            const float* xb = xbase + (t0 + TTILE) * VV;
            #pragma unroll
            for (int k = 0; k < 13; k++) {
                int i = tid + k*256;
                if (i < RAW_F/4) {
                    int c = i / 50, qq = i - c*50;
                    cp_async16(raw + c*(TTILE*VV) + qq*4, xb + c*(TT*VV) + qq*4);
                }
            }
            CP_COMMIT();
        }

        // ---- FFMA2 mainloop ----
        u64 acc0[13], acc1[13];
        {
            float b0 = bfs[d0], b1 = bfs[d0+1];
            u64 bb0 = pack2(b0, b0), bb1 = pack2(b1, b1);
            #pragma unroll
            for (int vp = 0; vp < 13; vp++) { acc0[vp] = bb0; acc1[vp] = bb1; }
        }
        #pragma unroll 4
        for (int c = 0; c < CC; c++) {
            float2 wv = *(const float2*)(Wfs + c*DD + d0);
            u64 s0 = pack2(wv.x, wv.x);
            u64 s1 = pack2(wv.y, wv.y);
            const float* ar = At + c*ATSTRIDE;
            #pragma unroll
            for (int p = 0; p < 6; p++) {
                ulonglong2 a2 = ((const ulonglong2*)ar)[p];
                acc0[2*p]   = ffma2(a2.x, s0, acc0[2*p]);
                acc1[2*p]   = ffma2(a2.x, s1, acc1[2*p]);
                acc0[2*p+1] = ffma2(a2.y, s0, acc0[2*p+1]);
                acc1[2*p+1] = ffma2(a2.y, s1, acc1[2*p+1]);
            }
            u64 a12 = ((const u64*)ar)[12];
            acc0[12] = ffma2(a12, s0, acc0[12]);
            acc1[12] = ffma2(a12, s1, acc1[12]);
        }

        // ---- epilogue: unpack, store y, stage sums ----
        float va[13][2], vb[13][2];
        #pragma unroll
        for (int vp = 0; vp < 13; vp++) {
            unpack2(acc0[vp], va[vp][0], va[vp][1]);
            unpack2(acc1[vp], vb[vp][0], vb[vp][1]);
        }
        float* yrow = g_y + (size_t)(n*TT + t0 + w) * FEAT;
        #pragma unroll
        for (int vp = 0; vp < 13; vp++) {
            int v = 2*vp;
            *(float2*)(yrow + v*DD + d0) = make_float2(va[vp][0], vb[vp][0]);
            if (v + 1 < VV)
                *(float2*)(yrow + (v+1)*DD + d0) = make_float2(va[vp][1], vb[vp][1]);
        }
        // stats round A: per-warp sums into (dead) At region, f-layout
        float* stg = Ats + w * TM_F;
        #pragma unroll
        for (int vp = 0; vp < 13; vp++) {
            int v = 2*vp;
            stg[v*DD + d0]     = va[vp][0];
            stg[v*DD + d0 + 1] = vb[vp][0];
            if (v + 1 < VV) {
                stg[(v+1)*DD + d0]     = va[vp][1];
                stg[(v+1)*DD + d0 + 1] = vb[vp][1];
            }
        }
        __syncthreads();
        for (int f = tid; f < FEAT; f += 256) {
            float s = 0.f;
            #pragma unroll
            for (int w8 = 0; w8 < 8; w8++) s += Ats[w8*TM_F + f];
            ssum[f] += s;
        }
        __syncthreads();
        // stats round B: squares
        #pragma unroll
        for (int vp = 0; vp < 13; vp++) {
            int v = 2*vp;
            stg[v*DD + d0]     = va[vp][0]*va[vp][0];
            stg[v*DD + d0 + 1] = vb[vp][0]*vb[vp][0];
            if (v + 1 < VV) {
                stg[(v+1)*DD + d0]     = va[vp][1]*va[vp][1];
                stg[(v+1)*DD + d0 + 1] = vb[vp][1]*vb[vp][1];
            }
        }
        __syncthreads();
        for (int f = tid; f < FEAT; f += 256) {
            float s = 0.f;
            #pragma unroll
            for (int w8 = 0; w8 < 8; w8++) s += Ats[w8*TM_F + f];
            ssq[f] += s;
        }
        // loop-top __syncthreads protects Ats reuse by next gather
    }
    __syncthreads();
    for (int f = tid; f < FEAT; f += 256) {
        atomicAdd(&g_sum[f], ssum[f]);
        atomicAdd(&g_sumsq[f], ssq[f]);
    }
}

// ---------------- kernel 6: finalize BN params (with shift_out fold) ---------
__global__ void finalize_kernel(const int* __restrict__ shift_out,
                                const float* __restrict__ gamma,
                                const float* __restrict__ beta) {
    int f = blockIdx.x * 256 + threadIdx.x;
    if (f >= FEAT) return;
    int s = shift_out[f];
    const float invn = 1.0f / (float)ROWS;
    float mu = g_sum[s] * invn;
    float var = g_sumsq[s] * invn - mu * mu;
    float sc = gamma[f] * rsqrtf(var + 1e-5f);
    g_scale[f] = sc;
    g_bias[f] = beta[f] - mu * sc;
}

// ---------------- kernel 7: shift-out + BN + residual + relu + transpose -----
#define ZSTRIDE 1632                     // 25*65 pad + align
#define FINAL_SMEM_BYTES ((TTILE*FEAT + 4*ZSTRIDE)*4)
__global__ void __launch_bounds__(256, 2) final_kernel(const float* __restrict__ x0,
                                                       const int* __restrict__ shift_out,
                                                       float* __restrict__ out) {
    extern __shared__ float fs[];
    float* ysm = fs;                      // 8 x 1600
    float* zsm = fs + TTILE*FEAT;         // 4 x 1632 (v*65+d layout)

    int bid = blockIdx.x;
    int n  = bid >> 5;
    int t0 = (bid & 31) * TTILE;
    int tid = threadIdx.x;

    {
        const float4* ys = (const float4*)(g_y + (size_t)(n*TT + t0) * FEAT);
        float4* yd = (float4*)ysm;
        for (int i = tid; i < (TTILE*FEAT)/4; i += 256) yd[i] = ys[i];
    }
    __syncthreads();

    size_t nbase = (size_t)n * CC * (TT*VV);
    #pragma unroll
    for (int half = 0; half < 2; half++) {
        #pragma unroll
        for (int tl = 0; tl < 4; tl++) {
            const float* yr = ysm + (half*4 + tl)*FEAT;
            for (int f = tid; f < FEAT; f += 256) {
                int v = f >> 6, d = f & 63;
                float val = yr[shift_out[f]] * g_scale[f] + g_bias[f];
                zsm[tl*ZSTRIDE + v*65 + d] = val;
            }
        }
        __syncthreads();
        for (int e = tid; e < 4*FEAT; e += 256) {
            int d = e / 100;
            int r = e - d * 100;
            int tl = r / 25;
            int v = r - tl * 25;
            float z = zsm[tl*ZSTRIDE + v*65 + d];
            size_t idx = nbase + (size_t)d * (TT*VV) + (size_t)(t0 + half*4 + tl) * VV + v;
            float o = z + x0[idx];
            out[idx] = o > 0.f ? o : 0.f;
        }
        __syncthreads();
    }
}

// ---------------- launcher ---------------------------------------------------
extern "C" void kernel_launch(void* const* d_in, const int* in_sizes, int n_in,
                              void* d_out, int out_size) {
    const float* x0       = (const float*)d_in[0];
    const int*   epoch    = (const int*)  d_in[1];
    const float* fc1_w    = (const float*)d_in[2];
    const float* fc1_b    = (const float*)d_in[3];
    const float* fc2_w    = (const float*)d_in[4];
    const float* fc2_b    = (const float*)d_in[5];
    const float* W        = (const float*)d_in[6];
    const float* b        = (const float*)d_in[7];
    const float* mask     = (const float*)d_in[8];
    const float* gamma    = (const float*)d_in[9];
    const float* beta     = (const float*)d_in[10];
    const int*   shift_in = (const int*)  d_in[11];
    const int*   shift_out= (const int*)  d_in[12];
    float* out = (float*)d_out;

    cudaFuncSetAttribute(gemm_kernel, cudaFuncAttributeMaxDynamicSharedMemorySize, GEMM_SMEM_BYTES);
    cudaFuncSetAttribute(final_kernel, cudaFuncAttributeMaxDynamicSharedMemorySize, FINAL_SMEM_BYTES);

    pool_kernel<<<NN*CC, 256>>>(x0);
    gate_kernel<<<1, 128>>>(fc1_w, fc1_b, fc2_w, fc2_b, epoch);
    prep_kernel<<<NN + 1, 256>>>(W, b, mask, shift_in);
    gemm_kernel<<<NN * 8, 256, GEMM_SMEM_BYTES>>>(x0);
    finalize_kernel<<<(FEAT + 255)/256, 256>>>(shift_out, gamma, beta);
    final_kernel<<<NN * (TT/TTILE), 256, FINAL_SMEM_BYTES>>>(x0, shift_out, out);
}

// round 4
// speedup vs baseline: 2.6572x; 1.4826x over previous
#include <cuda_runtime.h>
#include <cstdint>

// Problem constants
#define NN 128
#define CC 64
#define TT 256
#define VV 25
#define DD 64
#define RR 16           // SE reduction dim (C/4)
#define FEAT 1600       // V*D
#define ROWS (NN*TT)    // 32768
#define TTILE 8         // t-frames per gemm tile
#define NTILES 4        // tiles per block
#define ATSTRIDE 28     // padded v-dim (16B-aligned rows for LDS.128)
#define ATW (CC*ATSTRIDE)   // 1792 floats per warp region

typedef unsigned long long u64;

// ---------------- scratch (device globals; no allocations allowed) ----------
__device__ float g_pooled[NN*CC];
__device__ float g_gate[NN*4];
__device__ float g_Wf[NN*CC*DD];      // 2 MB
__device__ float g_bf[NN*DD];
__device__ float g_z[(size_t)NN*CC*TT*VV]; // 209.7 MB, OUTPUT layout [n][d][t][v], pre-BN
__device__ float g_sum[FEAT];
__device__ float g_sumsq[FEAT];
__device__ float g_scale[FEAT];
__device__ float g_bias[FEAT];
__device__ short g_tsrc[CC*ATSTRIDE];  // gather table into raw smem tile
__device__ float g_tm[CC*ATSTRIDE];    // tanh(mask)+1, 0 on pad slots
__device__ short g_inv[FEAT];          // inv_pad: s -> f+(f>>6) where shift_out[f]=s

// ---------------- f32x2 helpers ---------------------------------------------
__device__ __forceinline__ u64 pack2(float lo, float hi) {
    u64 r; asm("mov.b64 %0, {%1, %2};" : "=l"(r) : "f"(lo), "f"(hi)); return r;
}
__device__ __forceinline__ void unpack2(u64 v, float& lo, float& hi) {
    asm("mov.b64 {%0, %1}, %2;" : "=f"(lo), "=f"(hi) : "l"(v));
}
__device__ __forceinline__ u64 ffma2(u64 a, u64 b, u64 c) {
    u64 d; asm("fma.rn.f32x2 %0, %1, %2, %3;" : "=l"(d) : "l"(a), "l"(b), "l"(c));
    return d;
}
__device__ __forceinline__ void cp_async16(float* dst_smem, const void* src) {
    unsigned d = (unsigned)__cvta_generic_to_shared(dst_smem);
    asm volatile("cp.async.cg.shared.global [%0], [%1], 16;" :: "r"(d), "l"(src));
}
#define CP_COMMIT() asm volatile("cp.async.commit_group;")
#define CP_WAIT0()  asm volatile("cp.async.wait_group 0;")

// ---------------- kernel 1: global average pool ------------------------------
__global__ void pool_kernel(const float* __restrict__ x0) {
    int nc = blockIdx.x;                 // 0..8191  (n*64 + c)
    const float4* p = (const float4*)(x0 + (size_t)nc * (TT*VV));
    float s = 0.f;
    for (int i = threadIdx.x; i < (TT*VV)/4; i += 256) {
        float4 v = p[i];
        s += v.x + v.y + v.z + v.w;
    }
    for (int off = 16; off > 0; off >>= 1) s += __shfl_down_sync(0xffffffffu, s, off);
    __shared__ float red[8];
    int w = threadIdx.x >> 5, l = threadIdx.x & 31;
    if (l == 0) red[w] = s;
    __syncthreads();
    if (threadIdx.x == 0) {
        float t = 0.f;
        #pragma unroll
        for (int i = 0; i < 8; i++) t += red[i];
        g_pooled[nc] = t * (1.f / (TT*VV));
    }
}

// ---------------- kernel 2: SE gate ------------------------------------------
__global__ void gate_kernel(const float* __restrict__ fc1_w, const float* __restrict__ fc1_b,
                            const float* __restrict__ fc2_w, const float* __restrict__ fc2_b,
                            const int* __restrict__ epoch_p) {
    int n = threadIdx.x;
    if (n >= NN) return;
    float pooled[CC];
    #pragma unroll
    for (int c = 0; c < CC; c++) pooled[c] = g_pooled[n*CC + c];
    float h[RR];
    #pragma unroll
    for (int j = 0; j < RR; j++) {
        float s = fc1_b[j];
        #pragma unroll
        for (int c = 0; c < CC; c++) s += pooled[c] * fc1_w[j*CC + c];
        h[j] = s > 0.f ? s : 0.f;
    }
    float lg[4];
    #pragma unroll
    for (int k = 0; k < 4; k++) {
        float s = fc2_b[k];
        #pragma unroll
        for (int j = 0; j < RR; j++) s += h[j] * fc2_w[k*RR + j];
        lg[k] = s;
    }
    int ep = *epoch_p;
    float tao = (ep >= 60) ? 1.0f : (-(29.0f / 60.0f) * (float)ep + 30.0f);
    float inv = 1.0f / tao;
    float m = lg[0];
    #pragma unroll
    for (int k = 1; k < 4; k++) m = fmaxf(m, lg[k]);
    float e[4], sum = 0.f;
    #pragma unroll
    for (int k = 0; k < 4; k++) { e[k] = __expf((lg[k] - m) * inv); sum += e[k]; }
    float r = 1.0f / sum;
    #pragma unroll
    for (int k = 0; k < 4; k++) g_gate[n*4 + k] = e[k] * r;
}

// ---------------- kernel 3: fused weights + tables + zero stats --------------
__global__ void prep_kernel(const float* __restrict__ W, const float* __restrict__ b,
                            const float* __restrict__ mask, const int* __restrict__ shift_in,
                            const int* __restrict__ shift_out) {
    int blk = blockIdx.x;
    int tid = threadIdx.x;
    if (blk < NN) {
        int n = blk;
        float g0 = g_gate[n*4+0], g1 = g_gate[n*4+1], g2 = g_gate[n*4+2], g3 = g_gate[n*4+3];
        for (int i = tid; i < CC*DD; i += 256)
            g_Wf[n*CC*DD + i] = g0*W[i] + g1*W[CC*DD + i] + g2*W[2*CC*DD + i] + g3*W[3*CC*DD + i];
        if (tid < DD)
            g_bf[n*DD + tid] = g0*b[tid] + g1*b[DD+tid] + g2*b[2*DD+tid] + g3*b[3*DD+tid];
    } else {
        for (int j = tid; j < CC*ATSTRIDE; j += 256) {
            int c_out = j / ATSTRIDE, v_out = j % ATSTRIDE;
            if (v_out < VV) {
                int src = shift_in[v_out*CC + c_out];
                int vp = src >> 6, cp = src & 63;          // C == 64
                g_tsrc[j] = (short)(cp * (TTILE*VV) + vp); // index into raw smem tile
                g_tm[j] = tanhf(mask[v_out*CC + c_out]) + 1.0f;
            } else {
                g_tsrc[j] = 0;
                g_tm[j] = 0.f;
            }
        }
        for (int f = tid; f < FEAT; f += 256) {
            g_sum[f] = 0.f; g_sumsq[f] = 0.f;
            int s = shift_out[f];                   // bijection: invert it
            g_inv[s] = (short)(f + (f >> 6));       // padded v*65+d offset
        }
    }
}

// ---------------- kernel 4: persistent pipelined GEMM + scatter + stats ------
// 1024 blocks; block = (n = bid>>3, q8 = bid&7); 4 tiles of 8 frames.
// 8 warps; warp w = frame w; lane l owns d-pair (2l, 2l+1), all 25 v.
// Epilogue: scatter z=y[shift_out^-1] into (dead) At region padded v*65+d,
// register-accumulate BN stats, coalesced transposed store to g_z [n][d][t][v].
#define RAW_F (CC*TTILE*VV)        // 12800
#define AT_F  (8*ATW)              // 14336
#define WF_F  (CC*DD)              // 4096
#define GEMM_SMEM_BYTES ((RAW_F + AT_F + WF_F + ATW + DD)*4 + (ATW + FEAT)*2)

__global__ void __launch_bounds__(256, 1) gemm_kernel(const float* __restrict__ x0) {
    extern __shared__ float smem[];
    float* raw  = smem;                 // [c][t][v] 64 x 200
    float* Ats  = raw + RAW_F;          // 8 x [c][28]; aliased as scatter buf [v*65+d]
    float* Wfs  = Ats + AT_F;           // [c][d]
    float* tms  = Wfs + WF_F;           // 64 x 28
    float* bfs  = tms + ATW;            // [64]
    short* tss  = (short*)(bfs + DD);   // 64 x 28
    short* invs = tss + ATW;            // [1600]

    int bid = blockIdx.x;
    int n   = bid >> 3;
    int q8  = bid & 7;
    int tid = threadIdx.x;
    int w = tid >> 5, l = tid & 31;

    { // block-start staging (covered by first loop-top sync)
        const float4* ws = (const float4*)(g_Wf + (size_t)n * WF_F);
        float4* wd = (float4*)Wfs;
        for (int i = tid; i < WF_F/4; i += 256) wd[i] = ws[i];
        for (int j = tid; j < ATW; j += 256) { tms[j] = g_tm[j]; tss[j] = g_tsrc[j]; }
        for (int f = tid; f < FEAT; f += 256) invs[f] = g_inv[f];
        if (tid < DD) bfs[tid] = g_bf[n*DD + tid];
    }

    const float* xbase = x0 + (size_t)n * CC * (TT*VV);

    // prefetch tile 0
    {
        const float* xb = xbase + (q8*32) * VV;
        #pragma unroll
        for (int k = 0; k < 13; k++) {
            int i = tid + k*256;
            if (i < RAW_F/4) {
                int c = i / 50, qq = i - c*50;
                cp_async16(raw + c*(TTILE*VV) + qq*4, xb + c*(TT*VV) + qq*4);
            }
        }
        CP_COMMIT();
    }

    int d0 = 2*l;
    float* At = Ats + w * ATW;
    const float* rw = raw + w * VV;

    float rsum[7], rsq[7];
    #pragma unroll
    for (int k = 0; k < 7; k++) { rsum[k] = 0.f; rsq[k] = 0.f; }

    for (int it = 0; it < NTILES; it++) {
        int t0 = q8*32 + it*TTILE;
        CP_WAIT0();
        __syncthreads();                       // raw ready; prev epilogue consumed

        // gather + mask into transposed padded At[c][28]
        #pragma unroll 4
        for (int j = l; j < ATW; j += 32) At[j] = rw[tss[j]] * tms[j];
        __syncthreads();                       // raw now free

        // prefetch next tile (DMA overlaps compute)
        if (it + 1 < NTILES) {
            const float* xb = xbase + (t0 + TTILE) * VV;
            #pragma unroll
            for (int k = 0; k < 13; k++) {
                int i = tid + k*256;
                if (i < RAW_F/4) {
                    int c = i / 50, qq = i - c*50;
                    cp_async16(raw + c*(TTILE*VV) + qq*4, xb + c*(TT*VV) + qq*4);
                }
            }
            CP_COMMIT();
        }

        // ---- FFMA2 mainloop ----
        u64 acc0[13], acc1[13];
        {
            float b0 = bfs[d0], b1 = bfs[d0+1];
            u64 bb0 = pack2(b0, b0), bb1 = pack2(b1, b1);
            #pragma unroll
            for (int vp = 0; vp < 13; vp++) { acc0[vp] = bb0; acc1[vp] = bb1; }
        }
        #pragma unroll 4
        for (int c = 0; c < CC; c++) {
            float2 wv = *(const float2*)(Wfs + c*DD + d0);
            u64 s0 = pack2(wv.x, wv.x);
            u64 s1 = pack2(wv.y, wv.y);
            const float* ar = At + c*ATSTRIDE;
            #pragma unroll
            for (int p = 0; p < 6; p++) {
                ulonglong2 a2 = ((const ulonglong2*)ar)[p];
                acc0[2*p]   = ffma2(a2.x, s0, acc0[2*p]);
                acc1[2*p]   = ffma2(a2.x, s1, acc1[2*p]);
                acc0[2*p+1] = ffma2(a2.y, s0, acc0[2*p+1]);
                acc1[2*p+1] = ffma2(a2.y, s1, acc1[2*p+1]);
            }
            u64 a12 = ((const u64*)ar)[12];
            acc0[12] = ffma2(a12, s0, acc0[12]);
            acc1[12] = ffma2(a12, s1, acc1[12]);
        }

        // ---- epilogue: scatter through inverse shift_out into own At region ---
        // (warp-synchronous: all mainloop reads of At precede these writes)
        #pragma unroll
        for (int vp = 0; vp < 13; vp++) {
            float a0, a1, c0, c1;
            unpack2(acc0[vp], a0, a1);
            unpack2(acc1[vp], c0, c1);
            int v = 2*vp;
            int sb = v*DD + d0;
            At[invs[sb]]     = a0;
            At[invs[sb + 1]] = c0;
            if (v + 1 < VV) {
                At[invs[sb + DD]]     = a1;
                At[invs[sb + DD + 1]] = c1;
            }
        }
        __syncthreads();                       // all z-tiles staged

        // stats: thread owns fixed f-slots, accumulate in registers
        #pragma unroll
        for (int k = 0; k < 7; k++) {
            int f = tid + k*256;
            if (f < FEAT) {
                int pa = f + (f >> 6);
                float s = 0.f, q = 0.f;
                #pragma unroll
                for (int w8 = 0; w8 < 8; w8++) {
                    float v = Ats[w8*ATW + pa];
                    s += v; q += v*v;
                }
                rsum[k] += s; rsq[k] += q;
            }
        }
        // transposed coalesced store to g_z [n][d][t][v]
        {
            float* zb = g_z + (size_t)n * (CC*TT*VV) + (size_t)t0 * VV;
            #pragma unroll
            for (int k = 0; k < 13; k++) {
                int qd = tid + k*256;              // quad id, 3200 total
                if (qd < 3200) {
                    int e = qd*4;
                    int d = e / 200;
                    int r = e - d*200;             // multiple of 4, <= 196
                    float4 o;
                    #pragma unroll
                    for (int j = 0; j < 4; j++) {
                        int rr = r + j;
                        int tlj = rr / 25;
                        int vj = rr - tlj*25;
                        ((float*)&o)[j] = Ats[tlj*ATW + vj*65 + d];
                    }
                    *(float4*)(zb + (size_t)d*(TT*VV) + r) = o;
                }
            }
        }
        // loop-top sync protects Ats reuse by next gather
    }
    __syncthreads();
    #pragma unroll
    for (int k = 0; k < 7; k++) {
        int f = tid + k*256;
        if (f < FEAT) {
            atomicAdd(&g_sum[f], rsum[k]);
            atomicAdd(&g_sumsq[f], rsq[k]);
        }
    }
}

// ---------------- kernel 5: finalize BN params (f-space, no indirection) -----
__global__ void finalize_kernel(const float* __restrict__ gamma,
                                const float* __restrict__ beta) {
    int f = blockIdx.x * 256 + threadIdx.x;
    if (f >= FEAT) return;
    const float invn = 1.0f / (float)ROWS;
    float mu = g_sum[f] * invn;
    float var = g_sumsq[f] * invn - mu * mu;
    float sc = gamma[f] * rsqrtf(var + 1e-5f);
    g_scale[f] = sc;
    g_bias[f] = beta[f] - mu * sc;
}

// ---------------- kernel 6: elementwise BN + residual + relu -----------------
// block = (n, d): 6400 contiguous elements; f = v*64+d, v = idx%25.
__global__ void __launch_bounds__(256) final_kernel(const float* __restrict__ x0,
                                                    float* __restrict__ out) {
    __shared__ float sc[VV], bi[VV];
    int b = blockIdx.x;
    int n = b >> 6, d = b & 63;
    int tid = threadIdx.x;
    if (tid < VV) {
        sc[tid] = g_scale[tid*DD + d];
        bi[tid] = g_bias[tid*DD + d];
    }
    __syncthreads();
    size_t base = (size_t)n * (CC*TT*VV) + (size_t)d * (TT*VV);
    const float4* zp = (const float4*)(g_z + base);
    const float4* xp = (const float4*)(x0 + base);
    float4* op = (float4*)(out + base);
    #pragma unroll
    for (int k = 0; k < 7; k++) {
        int q = tid + k*256;
        if (q < (TT*VV)/4) {
            int e = q*4;
            int v0 = e - (e/25)*25;
            float4 z = zp[q], x = xp[q], o;
            #pragma unroll
            for (int j = 0; j < 4; j++) {
                int v = v0 + j; if (v >= VV) v -= VV;
                float val = ((const float*)&z)[j] * sc[v] + bi[v] + ((const float*)&x)[j];
                ((float*)&o)[j] = val > 0.f ? val : 0.f;
            }
            op[q] = o;
        }
    }
}

// ---------------- launcher ---------------------------------------------------
extern "C" void kernel_launch(void* const* d_in, const int* in_sizes, int n_in,
                              void* d_out, int out_size) {
    const float* x0       = (const float*)d_in[0];
    const int*   epoch    = (const int*)  d_in[1];
    const float* fc1_w    = (const float*)d_in[2];
    const float* fc1_b    = (const float*)d_in[3];
    const float* fc2_w    = (const float*)d_in[4];
    const float* fc2_b    = (const float*)d_in[5];
    const float* W        = (const float*)d_in[6];
    const float* b        = (const float*)d_in[7];
    const float* mask     = (const float*)d_in[8];
    const float* gamma    = (const float*)d_in[9];
    const float* beta     = (const float*)d_in[10];
    const int*   shift_in = (const int*)  d_in[11];
    const int*   shift_out= (const int*)  d_in[12];
    float* out = (float*)d_out;

    cudaFuncSetAttribute(gemm_kernel, cudaFuncAttributeMaxDynamicSharedMemorySize, GEMM_SMEM_BYTES);

    pool_kernel<<<NN*CC, 256>>>(x0);
    gate_kernel<<<1, 128>>>(fc1_w, fc1_b, fc2_w, fc2_b, epoch);
    prep_kernel<<<NN + 1, 256>>>(W, b, mask, shift_in, shift_out);
    gemm_kernel<<<NN * 8, 256, GEMM_SMEM_BYTES>>>(x0);
    finalize_kernel<<<(FEAT + 255)/256, 256>>>(gamma, beta);
    final_kernel<<<NN * CC, 256>>>(x0, out);
}